// round 14
// baseline (speedup 1.0000x reference)
#include <cuda_runtime.h>
#include <cuda_bf16.h>
#include <cuda_fp16.h>
#include <cstdint>

// ---------------- problem constants ----------------
#define Bb    4
#define Nn    4096
#define Eraw  131072
#define Etot  (Eraw + Nn)        // 135168 (self loops appended)
#define Fin   768
#define HIDD  64
#define NHEAD 4
#define HD    256                // NHEAD * HIDD
#define NCLS  6
#define Mtot  (Bb * Nn)          // 16384
#define MHALF (Mtot / 2)         // 8192

#define WT1   (HD * Fin)
#define WT2   (HD * HD)
#define WT3   (HIDD * HD)
#define WTALL (WT1 + WT2 + WT3)
#define XUNITS (Mtot * Fin / 4)
#define XBLKS  (XUNITS / 256)
#define WTBLKS (WTALL / 256)
#define CNTBLKS ((Bb * Nn) / 256)

#define SM_A_BUF   20480
#define SM_B_OFF   (2 * SM_A_BUF)
#define SM_B_BUF   10240
#define SM_DYN     (SM_B_OFF + 2 * SM_B_BUF)

// ---------------- scratch (double-buffered per layer parity) ----------------
__device__ __half g_hhA[Mtot * HD];
__device__ __half g_hhB[Mtot * HD];
__device__ __nv_bfloat16 g_oh[Mtot * HD];
__device__ __nv_bfloat16 g_ol[Mtot * HD];
__device__ __nv_bfloat16 g_xh[Mtot * Fin];
__device__ __nv_bfloat16 g_xl[Mtot * Fin];
__device__ __nv_bfloat16 g_wth[WTALL];
__device__ __nv_bfloat16 g_wtl[WTALL];
__device__ float g_asA[Mtot * NHEAD];
__device__ float g_adA[Mtot * NHEAD];
__device__ float g_asB[Mtot * NHEAD];
__device__ float g_adB[Mtot * NHEAD];
__device__ int   g_cnt[Bb * Nn];
__device__ int   g_rp [Bb * (Nn + 1)];
__device__ int   g_cur[Bb * Nn];
__device__ int   g_csrc[Bb * Etot];
__device__ float g_emb[Bb * HIDD];

// ---------------- helpers ----------------
__device__ __forceinline__ uint32_t pack_bf(__nv_bfloat16 a, __nv_bfloat16 b) {
    return ((uint32_t)__bfloat16_as_ushort(b) << 16) | (uint32_t)__bfloat16_as_ushort(a);
}

__device__ __forceinline__ void ldsm4u(uint32_t* r, uint32_t a) {
    asm volatile("ldmatrix.sync.aligned.m8n8.x4.shared.b16 {%0,%1,%2,%3}, [%4];"
        : "=r"(r[0]), "=r"(r[1]), "=r"(r[2]), "=r"(r[3]) : "r"(a));
}

__device__ __forceinline__ void mma16816(float* d, const uint32_t* a, const uint32_t* b) {
    asm volatile("mma.sync.aligned.m16n8k16.row.col.f32.bf16.bf16.f32 "
        "{%0,%1,%2,%3}, {%4,%5,%6,%7}, {%8,%9}, {%0,%1,%2,%3};"
        : "+f"(d[0]), "+f"(d[1]), "+f"(d[2]), "+f"(d[3])
        : "r"(a[0]), "r"(a[1]), "r"(a[2]), "r"(a[3]), "r"(b[0]), "r"(b[1]));
}

__device__ __forceinline__ void cp16(uint32_t dst, const void* src) {
    asm volatile("cp.async.cg.shared.global [%0], [%1], 16;" :: "r"(dst), "l"(src));
}

__device__ __forceinline__ float leaky_exp(float eh) {
    eh = (eh > 0.f) ? eh : 0.2f * eh;
    return __expf(eh);
}

// ---------------- fused conversions + zero emb -------------
__global__ void k_cvt(const float* __restrict__ x, const float* __restrict__ W1,
                      const float* __restrict__ W2, const float* __restrict__ W3) {
    int b = blockIdx.x;
    if (b < XBLKS) {
        int i = b * 256 + threadIdx.x;
        float4 v = ((const float4*)x)[i];
        __nv_bfloat16 h0 = __float2bfloat16(v.x), h1 = __float2bfloat16(v.y);
        __nv_bfloat16 h2 = __float2bfloat16(v.z), h3 = __float2bfloat16(v.w);
        __nv_bfloat16 l0 = __float2bfloat16(v.x - __bfloat162float(h0));
        __nv_bfloat16 l1 = __float2bfloat16(v.y - __bfloat162float(h1));
        __nv_bfloat16 l2 = __float2bfloat16(v.z - __bfloat162float(h2));
        __nv_bfloat16 l3 = __float2bfloat16(v.w - __bfloat162float(h3));
        uint2 uh; uh.x = pack_bf(h0, h1); uh.y = pack_bf(h2, h3);
        uint2 ul; ul.x = pack_bf(l0, l1); ul.y = pack_bf(l2, l3);
        ((uint2*)g_xh)[i] = uh;
        ((uint2*)g_xl)[i] = ul;
    } else if (b < XBLKS + WTBLKS) {
        int i = (b - XBLKS) * 256 + threadIdx.x;
        float v;
        if (i < WT1) {
            int n = i / Fin, k = i - n * Fin;
            v = W1[k * HD + n];
        } else if (i < WT1 + WT2) {
            int j = i - WT1; int n = j / HD, k = j - n * HD;
            v = W2[k * HD + n];
        } else {
            int j = i - WT1 - WT2; int n = j / HD, k = j - n * HD;
            v = W3[k * HIDD + n];
        }
        __nv_bfloat16 h = __float2bfloat16(v);
        __nv_bfloat16 l = __float2bfloat16(v - __bfloat162float(h));
        g_wth[i] = h; g_wtl[i] = l;
    } else {
        g_emb[threadIdx.x] = 0.f;
    }
}

// ---------------- CSR build ----------------
__global__ void k_zero() {
    int i = blockIdx.x * blockDim.x + threadIdx.x;
    if (i < Bb * Nn) g_cnt[i] = 0;
}

__global__ void k_hist(const int* __restrict__ ei) {
    const int half = (Bb * Etot) / 2;
    int i = blockIdx.x * blockDim.x + threadIdx.x;
    if (i >= half) return;
#pragma unroll
    for (int r = 0; r < 2; r++) {
        int j = i + r * half;
        int g = j / Etot, e = j - g * Etot;
        int dst = (e < Eraw) ? ei[(g * 2 + 1) * Eraw + e] : (e - Eraw);
        atomicAdd(&g_cnt[g * Nn + dst], 1);
    }
}

__global__ void k_scan() {
    int g = blockIdx.x;
    __shared__ int sh[1024];
    int t = threadIdx.x;
    const int* cnt = g_cnt + g * Nn;
    int b4 = t * 4;
    int v0 = cnt[b4], v1 = cnt[b4 + 1], v2 = cnt[b4 + 2], v3 = cnt[b4 + 3];
    int s1 = v0, s2 = s1 + v1, s3 = s2 + v2, s4 = s3 + v3;
    sh[t] = s4;
    __syncthreads();
    for (int off = 1; off < 1024; off <<= 1) {
        int x = (t >= off) ? sh[t - off] : 0;
        __syncthreads();
        sh[t] += x;
        __syncthreads();
    }
    int base = sh[t] - s4;
    int* rp  = g_rp  + g * (Nn + 1);
    int* cur = g_cur + g * Nn;
    if (t == 0) rp[0] = 0;
    rp[b4 + 1] = base + s1; rp[b4 + 2] = base + s2;
    rp[b4 + 3] = base + s3; rp[b4 + 4] = base + s4;
    cur[b4] = base; cur[b4 + 1] = base + s1; cur[b4 + 2] = base + s2; cur[b4 + 3] = base + s3;
}

__global__ void k_scatter(const int* __restrict__ ei) {
    const int half = (Bb * Etot) / 2;
    int i = blockIdx.x * blockDim.x + threadIdx.x;
    if (i >= half) return;
#pragma unroll
    for (int r = 0; r < 2; r++) {
        int j = i + r * half;
        int g = j / Etot, e = j - g * Etot;
        int src, dst;
        if (e < Eraw) { src = ei[(g * 2) * Eraw + e]; dst = ei[(g * 2 + 1) * Eraw + e]; }
        else          { src = e - Eraw; dst = src; }
        int pos = atomicAdd(&g_cur[g * Nn + dst], 1);
        g_csrc[g * Etot + pos] = src;
    }
}

// ---------------- mma.sync bf16 GEMM (3-term hi/lo), cp.async double-buffered ---------
// row_base: starting output row (node) for this launch; grid.y covers the slice.
__global__ __launch_bounds__(256)
void mma_gemm(const __nv_bfloat16* __restrict__ Ah, const __nv_bfloat16* __restrict__ Al,
              const __nv_bfloat16* __restrict__ Bth, const __nv_bfloat16* __restrict__ Btl,
              __half* __restrict__ C, int K, int row_base,
              const float* __restrict__ atts, const float* __restrict__ attd,
              float* __restrict__ asout, float* __restrict__ adout) {
    extern __shared__ __align__(16) char dsm[];
    __shared__ float sas[128][2], sad[128][2];
    const uint32_t smb = (uint32_t)__cvta_generic_to_shared(dsm);

    const int tid  = threadIdx.x;
    const int lane = tid & 31;
    const int warp = tid >> 5;
    const int wm = warp >> 1, wn = warp & 1;
    const int row0 = row_base + blockIdx.y * 128;
    const int head = blockIdx.x;
    const int H = gridDim.x;
    const int Nfull = H * 64;
    const int n0 = head * 64;

    float d[2][4][4];
#pragma unroll
    for (int mi = 0; mi < 2; mi++)
#pragma unroll
        for (int ni = 0; ni < 4; ni++)
#pragma unroll
            for (int j = 0; j < 4; j++) d[mi][ni][j] = 0.f;

    const int a_u0r = tid >> 1, a_u0c = (tid & 1) * 16;
    const int b_u0r = tid >> 2, b_u0c = (tid & 3) * 8;

    auto issue = [&](int ch, int db) {
        const int k0 = ch << 5;
        uint32_t abase = smb + db * SM_A_BUF;
        uint32_t bbase = smb + SM_B_OFF + db * SM_B_BUF;
#pragma unroll
        for (int hl = 0; hl < 2; hl++) {
            const __nv_bfloat16* srcA = (hl ? Al : Ah) + (size_t)(row0 + a_u0r) * K + k0 + a_u0c;
            uint32_t dstA = abase + hl * 10240 + a_u0r * 80 + a_u0c * 2;
            cp16(dstA, srcA);
            cp16(dstA + 16, srcA + 8);
        }
#pragma unroll
        for (int hl = 0; hl < 2; hl++) {
            const __nv_bfloat16* srcB = (hl ? Btl : Bth) + (size_t)(n0 + b_u0r) * K + k0 + b_u0c;
            uint32_t dstB = bbase + hl * 5120 + b_u0r * 80 + b_u0c * 2;
            cp16(dstB, srcB);
        }
        asm volatile("cp.async.commit_group;" ::: "memory");
    };

    const int a_row = wm * 32 + (lane & 15);
    const int a_colbase = (lane >> 4) * 8;
    const int b_rowbase = wn * 32 + (lane >> 4) * 8 + (lane & 7);
    const int b_colbase = ((lane >> 3) & 1) * 8;

    const int nchunks = K >> 5;
    issue(0, 0);
    for (int ch = 0; ch < nchunks; ch++) {
        const int db = ch & 1;
        if (ch + 1 < nchunks) {
            issue(ch + 1, db ^ 1);
            asm volatile("cp.async.wait_group 1;" ::: "memory");
        } else {
            asm volatile("cp.async.wait_group 0;" ::: "memory");
        }
        __syncthreads();

        uint32_t abase = smb + db * SM_A_BUF;
        uint32_t bbase = smb + SM_B_OFF + db * SM_B_BUF;
#pragma unroll
        for (int ks = 0; ks < 2; ks++) {
            uint32_t ah[2][4], al[2][4];
#pragma unroll
            for (int mi = 0; mi < 2; mi++) {
                uint32_t ra = abase + (a_row + mi * 16) * 80 + (ks * 16 + a_colbase) * 2;
                ldsm4u(ah[mi], ra);
                ldsm4u(al[mi], ra + 10240);
            }
            uint32_t bh[4][2], bl[4][2];
#pragma unroll
            for (int nb2 = 0; nb2 < 2; nb2++) {
                uint32_t rb = bbase + (b_rowbase + nb2 * 16) * 80 + (ks * 16 + b_colbase) * 2;
                uint32_t t[4];
                ldsm4u(t, rb);
                bh[nb2 * 2][0] = t[0]; bh[nb2 * 2][1] = t[1];
                bh[nb2 * 2 + 1][0] = t[2]; bh[nb2 * 2 + 1][1] = t[3];
                ldsm4u(t, rb + 5120);
                bl[nb2 * 2][0] = t[0]; bl[nb2 * 2][1] = t[1];
                bl[nb2 * 2 + 1][0] = t[2]; bl[nb2 * 2 + 1][1] = t[3];
            }
#pragma unroll
            for (int mi = 0; mi < 2; mi++)
#pragma unroll
                for (int ni = 0; ni < 4; ni++) {
                    mma16816(d[mi][ni], ah[mi], bh[ni]);
                    mma16816(d[mi][ni], ah[mi], bl[ni]);
                    mma16816(d[mi][ni], al[mi], bh[ni]);
                }
        }
        __syncthreads();
    }

    const float* asp = atts + head * 64;
    const float* adp = attd + head * 64;
    float ps[4] = {0.f, 0.f, 0.f, 0.f}, pd[4] = {0.f, 0.f, 0.f, 0.f};
#pragma unroll
    for (int mi = 0; mi < 2; mi++) {
        int rA = row0 + wm * 32 + mi * 16 + (lane >> 2);
#pragma unroll
        for (int ni = 0; ni < 4; ni++) {
            float* dd = d[mi][ni];
            int c = wn * 32 + ni * 8 + (lane & 3) * 2;
            float2 f0; f0.x = dd[0]; f0.y = dd[1];
            float2 f1; f1.x = dd[2]; f1.y = dd[3];
            __half2 h0 = __float22half2_rn(f0);
            __half2 h1 = __float22half2_rn(f1);
            *(__half2*)&C[(size_t)rA * Nfull + n0 + c] = h0;
            *(__half2*)&C[(size_t)(rA + 8) * Nfull + n0 + c] = h1;
            float s0 = asp[c], s1 = asp[c + 1], d0 = adp[c], d1 = adp[c + 1];
            ps[mi * 2 + 0] += dd[0] * s0 + dd[1] * s1;
            pd[mi * 2 + 0] += dd[0] * d0 + dd[1] * d1;
            ps[mi * 2 + 1] += dd[2] * s0 + dd[3] * s1;
            pd[mi * 2 + 1] += dd[2] * d0 + dd[3] * d1;
        }
    }
#pragma unroll
    for (int j = 0; j < 4; j++) {
        ps[j] += __shfl_xor_sync(0xffffffffu, ps[j], 1);
        ps[j] += __shfl_xor_sync(0xffffffffu, ps[j], 2);
        pd[j] += __shfl_xor_sync(0xffffffffu, pd[j], 1);
        pd[j] += __shfl_xor_sync(0xffffffffu, pd[j], 2);
    }
    if ((lane & 3) == 0) {
#pragma unroll
        for (int mi = 0; mi < 2; mi++) {
            int rloc = wm * 32 + mi * 16 + (lane >> 2);
            sas[rloc][wn] = ps[mi * 2];     sad[rloc][wn] = pd[mi * 2];
            sas[rloc + 8][wn] = ps[mi * 2 + 1]; sad[rloc + 8][wn] = pd[mi * 2 + 1];
        }
    }
    __syncthreads();
    if (tid < 128) {
        asout[(size_t)(row0 + tid) * H + head] = sas[tid][0] + sas[tid][1];
        adout[(size_t)(row0 + tid) * H + head] = sad[tid][0] + sad[tid][1];
    }
}

// ---------------- single-pass edge-softmax + aggregation, H=4 (2 warps/node) ----------
template <bool DOELU>
__global__ __launch_bounds__(256)
void attn_agg4(const __half* __restrict__ hh, const float* __restrict__ as,
               const float* __restrict__ ad, const float* __restrict__ bias,
               int node_base) {
    constexpr int H = 4, CH = 256, PER = 8;
    __shared__ float sh_acc[4][32][PER + 1];
    __shared__ float sh_den[4];

    const int tid  = threadIdx.x;
    const int warp = tid >> 5, lane = tid & 31;
    const int pair = warp >> 1, half = warp & 1;
    const int w = node_base + blockIdx.x * 4 + pair;
    const int g = w >> 12, n = w & (Nn - 1);
    const int s = g_rp[g * (Nn + 1) + n], e = g_rp[g * (Nn + 1) + n + 1];
    const int mid = (s + e + 1) >> 1;
    const int lo = half ? mid : s;
    const int hi = half ? e : mid;

    const int head = lane >> 3;
    const float adh = ad[(size_t)w * H + head];
    const int ebase = g * Etot;
    const long long nb = (long long)g * Nn;

    float acc[PER];
#pragma unroll
    for (int k = 0; k < PER; k++) acc[k] = 0.f;
    float den = 0.f;

    union U4 { uint4 u; __half2 h2[4]; };

    int i = lo;
    for (; i + 2 <= hi; i += 2) {
        int s0 = g_csrc[ebase + i];
        int s1 = g_csrc[ebase + i + 1];
        float ex0 = leaky_exp(as[(nb + s0) * H + head] + adh);
        float ex1 = leaky_exp(as[(nb + s1) * H + head] + adh);
        den += ex0 + ex1;
        U4 a, b;
        a.u = __ldg((const uint4*)(hh + (nb + s0) * CH + lane * PER));
        b.u = __ldg((const uint4*)(hh + (nb + s1) * CH + lane * PER));
#pragma unroll
        for (int q = 0; q < 4; q++) {
            float2 fa = __half22float2(a.h2[q]);
            float2 fb = __half22float2(b.h2[q]);
            acc[q * 2 + 0] += ex0 * fa.x + ex1 * fb.x;
            acc[q * 2 + 1] += ex0 * fa.y + ex1 * fb.y;
        }
    }
    if (i < hi) {
        int s0 = g_csrc[ebase + i];
        float ex0 = leaky_exp(as[(nb + s0) * H + head] + adh);
        den += ex0;
        U4 a; a.u = __ldg((const uint4*)(hh + (nb + s0) * CH + lane * PER));
#pragma unroll
        for (int q = 0; q < 4; q++) {
            float2 fa = __half22float2(a.h2[q]);
            acc[q * 2 + 0] += ex0 * fa.x;
            acc[q * 2 + 1] += ex0 * fa.y;
        }
    }

    if (half == 1) {
#pragma unroll
        for (int k = 0; k < PER; k++) sh_acc[pair][lane][k] = acc[k];
        if (lane == 0) sh_den[pair] = den;
    }
    __syncthreads();
    if (half == 1) return;

#pragma unroll
    for (int k = 0; k < PER; k++) acc[k] += sh_acc[pair][lane][k];
    den += sh_den[pair];

    const float invh = 1.f / (den + 1e-16f);
    float v[PER];
#pragma unroll
    for (int k = 0; k < PER; k++) {
        float t = acc[k] * invh + bias[lane * PER + k];
        if (DOELU) t = (t > 0.f) ? t : expm1f(t);
        v[k] = t;
    }
    __nv_bfloat16 hb[PER], lb[PER];
#pragma unroll
    for (int k = 0; k < PER; k++) {
        hb[k] = __float2bfloat16(v[k]);
        lb[k] = __float2bfloat16(v[k] - __bfloat162float(hb[k]));
    }
    size_t base = (size_t)w * CH + lane * PER;
    uint4 uh, ul;
    uh.x = pack_bf(hb[0], hb[1]); uh.y = pack_bf(hb[2], hb[3]);
    uh.z = pack_bf(hb[4], hb[5]); uh.w = pack_bf(hb[6], hb[7]);
    ul.x = pack_bf(lb[0], lb[1]); ul.y = pack_bf(lb[2], lb[3]);
    ul.z = pack_bf(lb[4], lb[5]); ul.w = pack_bf(lb[6], lb[7]);
    *(uint4*)(g_oh + base) = uh;
    *(uint4*)(g_ol + base) = ul;
}

// ---------------- layer-3 agg (H=1) with FUSED graph-mean ----------------
__global__ __launch_bounds__(256)
void attn_agg1m(const __half* __restrict__ hh, const float* __restrict__ as,
                const float* __restrict__ ad, const float* __restrict__ bias) {
    __shared__ float sh_sum[64];
    int tid = threadIdx.x;
    int w = (blockIdx.x * blockDim.x + tid) >> 5;
    int lane = tid & 31;
    int g = w >> 12, n = w & (Nn - 1);
    int s = g_rp[g * (Nn + 1) + n], e = g_rp[g * (Nn + 1) + n + 1];
    const float adh = ad[w];
    const int ebase = g * Etot;
    const long long nb = (long long)g * Nn;

    if (tid < 64) sh_sum[tid] = 0.f;
    __syncthreads();

    float acc0 = 0.f, acc1 = 0.f, den = 0.f;
    int i = s;
    for (; i + 2 <= e; i += 2) {
        int s0 = g_csrc[ebase + i];
        int s1 = g_csrc[ebase + i + 1];
        float ex0 = leaky_exp(as[nb + s0] + adh);
        float ex1 = leaky_exp(as[nb + s1] + adh);
        den += ex0 + ex1;
        float2 f0 = __half22float2(__ldg((const __half2*)(hh + (nb + s0) * HIDD + lane * 2)));
        float2 f1 = __half22float2(__ldg((const __half2*)(hh + (nb + s1) * HIDD + lane * 2)));
        acc0 += ex0 * f0.x + ex1 * f1.x;
        acc1 += ex0 * f0.y + ex1 * f1.y;
    }
    if (i < e) {
        int s0 = g_csrc[ebase + i];
        float ex0 = leaky_exp(as[nb + s0] + adh);
        den += ex0;
        float2 f0 = __half22float2(__ldg((const __half2*)(hh + (nb + s0) * HIDD + lane * 2)));
        acc0 += ex0 * f0.x;
        acc1 += ex0 * f0.y;
    }
    const float invh = 1.f / (den + 1e-16f);
    float v0 = acc0 * invh + bias[lane * 2];
    float v1 = acc1 * invh + bias[lane * 2 + 1];

    atomicAdd(&sh_sum[lane * 2],     v0);
    atomicAdd(&sh_sum[lane * 2 + 1], v1);
    __syncthreads();
    if (tid < 64)
        atomicAdd(&g_emb[g * HIDD + tid], sh_sum[tid] * (1.f / Nn));
}

// ---------------- classifier + log-softmax + loss/pred ----------------
__global__ void k_final(const int* __restrict__ labels, const float* __restrict__ Wc,
                        const float* __restrict__ bc, float* __restrict__ out, int out_size) {
    __shared__ float lg[Bb][NCLS];
    __shared__ float nll[Bb];
    __shared__ float predf[Bb];
    int t = threadIdx.x;
    if (t < Bb * NCLS) {
        int g = t / NCLS, c = t - g * NCLS;
        float s = bc[c];
#pragma unroll 8
        for (int d = 0; d < HIDD; d++) s += g_emb[g * HIDD + d] * Wc[d * NCLS + c];
        lg[g][c] = s;
    }
    __syncthreads();
    if (t < Bb) {
        float mx = lg[t][0]; int am = 0;
#pragma unroll
        for (int c = 1; c < NCLS; c++) if (lg[t][c] > mx) { mx = lg[t][c]; am = c; }
        float se = 0.f;
#pragma unroll
        for (int c = 0; c < NCLS; c++) se += expf(lg[t][c] - mx);
        float lse = mx + logf(se);
        nll[t] = lse - lg[t][labels[t]];
        predf[t] = (float)am;
    }
    __syncthreads();
    if (t == 0) {
        float loss = (nll[0] + nll[1] + nll[2] + nll[3]) * 0.25f;
        if (out_size >= 9) {
            for (int g = 0; g < Bb; g++) { out[g] = predf[g]; out[4 + g] = (float)labels[g]; }
            out[8] = loss;
            for (int j = 9; j < out_size; j++) out[j] = 0.f;
        } else if (out_size == 1) {
            out[0] = loss;
        } else if (out_size == 4) {
            for (int g = 0; g < Bb; g++) out[g] = predf[g];
        } else if (out_size == 8) {
            for (int g = 0; g < Bb; g++) { out[g] = predf[g]; out[4 + g] = (float)labels[g]; }
        } else {
            for (int j = 0; j < out_size; j++) out[j] = loss;
        }
    }
}

// ---------------- host launcher: two-stream layer-boundary pipeline ----------------
extern "C" void kernel_launch(void* const* d_in, const int* in_sizes, int n_in,
                              void* d_out, int out_size) {
    const float* x      = (const float*)d_in[0];
    const int*   labels = (const int*)  d_in[1];
    const int*   ei     = (const int*)  d_in[2];
    const float* W1  = (const float*)d_in[3];
    const float* as1 = (const float*)d_in[4];
    const float* ad1 = (const float*)d_in[5];
    const float* b1  = (const float*)d_in[6];
    const float* W2  = (const float*)d_in[7];
    const float* as2 = (const float*)d_in[8];
    const float* ad2 = (const float*)d_in[9];
    const float* b2  = (const float*)d_in[10];
    const float* W3  = (const float*)d_in[11];
    const float* as3 = (const float*)d_in[12];
    const float* ad3 = (const float*)d_in[13];
    const float* b3  = (const float*)d_in[14];
    const float* Wc  = (const float*)d_in[15];
    const float* bc  = (const float*)d_in[16];
    float* out = (float*)d_out;

    __half *p_hhA, *p_hhB;
    __nv_bfloat16 *p_oh, *p_ol, *p_xh, *p_xl, *p_wth, *p_wtl;
    float *p_asA, *p_adA, *p_asB, *p_adB;
    cudaGetSymbolAddress((void**)&p_hhA, g_hhA);
    cudaGetSymbolAddress((void**)&p_hhB, g_hhB);
    cudaGetSymbolAddress((void**)&p_oh, g_oh);
    cudaGetSymbolAddress((void**)&p_ol, g_ol);
    cudaGetSymbolAddress((void**)&p_xh, g_xh);
    cudaGetSymbolAddress((void**)&p_xl, g_xl);
    cudaGetSymbolAddress((void**)&p_wth, g_wth);
    cudaGetSymbolAddress((void**)&p_wtl, g_wtl);
    cudaGetSymbolAddress((void**)&p_asA, g_asA);
    cudaGetSymbolAddress((void**)&p_adA, g_adA);
    cudaGetSymbolAddress((void**)&p_asB, g_asB);
    cudaGetSymbolAddress((void**)&p_adB, g_adB);

    cudaFuncSetAttribute(mma_gemm, cudaFuncAttributeMaxDynamicSharedMemorySize, SM_DYN);

    const int EBLK2 = ((Bb * Etot) / 2 + 255) / 256;

    // host-side stream/event objects (no device allocation; leaked intentionally —
    // kernel_launch is invoked only a handful of times)
    cudaStream_t side;
    cudaStreamCreateWithFlags(&side, cudaStreamNonBlocking);
    cudaEvent_t evF, evCsr, evG1, evG2a, evG2b, evG3b;
    cudaEventCreateWithFlags(&evF,   cudaEventDisableTiming);
    cudaEventCreateWithFlags(&evCsr, cudaEventDisableTiming);
    cudaEventCreateWithFlags(&evG1,  cudaEventDisableTiming);
    cudaEventCreateWithFlags(&evG2a, cudaEventDisableTiming);
    cudaEventCreateWithFlags(&evG2b, cudaEventDisableTiming);
    cudaEventCreateWithFlags(&evG3b, cudaEventDisableTiming);

    cudaEventRecord(evF, 0);
    cudaStreamWaitEvent(side, evF, 0);

    // side: CSR build (independent of conversions/GEMM1)
    k_zero<<<CNTBLKS, 256, 0, side>>>();
    k_hist<<<EBLK2, 256, 0, side>>>(ei);
    k_scan<<<Bb, 1024, 0, side>>>();
    k_scatter<<<EBLK2, 256, 0, side>>>(ei);
    cudaEventRecord(evCsr, side);

    // main: conversions + FULL layer-1 GEMM -> hhA, asA/adA
    k_cvt<<<XBLKS + WTBLKS + 1, 256>>>(x, W1, W2, W3);
    mma_gemm<<<dim3(NHEAD, Mtot / 128), 256, SM_DYN>>>(
        p_xh, p_xl, p_wth, p_wtl, p_hhA, Fin, 0, as1, ad1, p_asA, p_adA);
    cudaEventRecord(evG1, 0);

    // ---- layer-1 agg + layer-2 GEMM, split halves across both streams ----
    // stream0 chain:  agg1_a(nodes 0..8191)  -> gemm2_a(rows 0..8191)
    // side   chain:   agg1_b(nodes 8192..)   -> gemm2_b(rows 8192..)
    cudaStreamWaitEvent(0, evCsr, 0);
    attn_agg4<true><<<MHALF / 4, 256>>>(p_hhA, p_asA, p_adA, b1, 0);
    mma_gemm<<<dim3(NHEAD, MHALF / 128), 256, SM_DYN>>>(
        p_oh, p_ol, p_wth + WT1, p_wtl + WT1, p_hhB, HD, 0, as2, ad2, p_asB, p_adB);
    cudaEventRecord(evG2a, 0);

    cudaStreamWaitEvent(side, evG1, 0);
    attn_agg4<true><<<MHALF / 4, 256, 0, side>>>(p_hhA, p_asA, p_adA, b1, MHALF);
    mma_gemm<<<dim3(NHEAD, MHALF / 128), 256, SM_DYN, side>>>(
        p_oh, p_ol, p_wth + WT1, p_wtl + WT1, p_hhB, HD, MHALF, as2, ad2, p_asB, p_adB);
    cudaEventRecord(evG2b, side);

    // ---- layer-2 agg + layer-3 GEMM, same split (agg2 needs BOTH gemm2 halves) ----
    cudaStreamWaitEvent(0, evG2b, 0);
    attn_agg4<true><<<MHALF / 4, 256>>>(p_hhB, p_asB, p_adB, b2, 0);
    mma_gemm<<<dim3(1, MHALF / 128), 256, SM_DYN>>>(
        p_oh, p_ol, p_wth + WT1 + WT2, p_wtl + WT1 + WT2, p_hhA, HD, 0, as3, ad3, p_asA, p_adA);

    cudaStreamWaitEvent(side, evG2a, 0);
    attn_agg4<true><<<MHALF / 4, 256, 0, side>>>(p_hhB, p_asB, p_adB, b2, MHALF);
    mma_gemm<<<dim3(1, MHALF / 128), 256, SM_DYN, side>>>(
        p_oh, p_ol, p_wth + WT1 + WT2, p_wtl + WT1 + WT2, p_hhA, HD, MHALF, as3, ad3, p_asA, p_adA);
    cudaEventRecord(evG3b, side);

    // ---- layer-3 agg (needs both gemm3 halves) + classifier ----
    cudaStreamWaitEvent(0, evG3b, 0);
    attn_agg1m<<<Mtot / 8, 256>>>(p_hhA, p_asA, p_adA, b3);
    k_final<<<1, 32>>>(labels, Wc, bc, out, out_size);
}

// round 16
// speedup vs baseline: 1.0906x; 1.0906x over previous
#include <cuda_runtime.h>
#include <cuda_bf16.h>
#include <cuda_fp16.h>
#include <cstdint>

// ---------------- problem constants ----------------
#define Bb    4
#define Nn    4096
#define Eraw  131072
#define Etot  (Eraw + Nn)        // 135168 (self loops appended)
#define Fin   768
#define HIDD  64
#define NHEAD 4
#define HD    256                // NHEAD * HIDD
#define NCLS  6
#define Mtot  (Bb * Nn)          // 16384

#define WT1   (HD * Fin)         // 196608 (bf16 hi/lo, layer 1)
#define WT2   (HD * HD)          // 65536  (fp16 hi/lo, layer 2)
#define WT3   (HIDD * HD)        // 16384  (fp16 hi/lo, layer 3)
#define W23   (WT2 + WT3)        // 81920
#define XUNITS (Mtot * Fin / 4)
#define XBLKS  (XUNITS / 256)    // 12288
#define W1BLKS (WT1 / 256)       // 768
#define W23BLKS (W23 / 256)      // 320
#define CNTBLKS ((Bb * Nn) / 256)

// bf16 3-term GEMM smem (layer 1)
#define SM_A_BUF   20480
#define SM_B_OFF   (2 * SM_A_BUF)
#define SM_B_BUF   10240
#define SM_DYN     (SM_B_OFF + 2 * SM_B_BUF)   // 61440

// fp16 2-term GEMM smem (layers 2/3)
#define S16_A_BUF  10240                        // 128 rows * 80B
#define S16_B_OFF  (2 * S16_A_BUF)              // 20480
#define S16_B_BUF  10240                        // 2(hl) * 64 * 80
#define S16_DYN    (S16_B_OFF + 2 * S16_B_BUF)  // 40960

// ---------------- scratch ----------------
__device__ __half g_hh[Mtot * HD];           // GEMM output h (fp16, gather payload)
__device__ __half g_o16[Mtot * HD];          // layer output (fp16, next GEMM A)
__device__ __nv_bfloat16 g_xh[Mtot * Fin];   // x hi
__device__ __nv_bfloat16 g_xl[Mtot * Fin];   // x lo
__device__ __nv_bfloat16 g_wth[WT1];         // W1^T hi (bf16)
__device__ __nv_bfloat16 g_wtl[WT1];         // W1^T lo
__device__ __half g_w16h[W23];               // W2^T,W3^T hi (fp16)
__device__ __half g_w16l[W23];               // W2^T,W3^T lo
__device__ float g_as [Mtot * NHEAD];
__device__ float g_ad [Mtot * NHEAD];
__device__ int   g_cnt[Bb * Nn];
__device__ int   g_rp [Bb * (Nn + 1)];
__device__ int   g_cur[Bb * Nn];
__device__ int   g_csrc[Bb * Etot];
__device__ float g_emb[Bb * HIDD];

// ---------------- helpers ----------------
__device__ __forceinline__ uint32_t pack_bf(__nv_bfloat16 a, __nv_bfloat16 b) {
    return ((uint32_t)__bfloat16_as_ushort(b) << 16) | (uint32_t)__bfloat16_as_ushort(a);
}

__device__ __forceinline__ void ldsm4u(uint32_t* r, uint32_t a) {
    asm volatile("ldmatrix.sync.aligned.m8n8.x4.shared.b16 {%0,%1,%2,%3}, [%4];"
        : "=r"(r[0]), "=r"(r[1]), "=r"(r[2]), "=r"(r[3]) : "r"(a));
}

__device__ __forceinline__ void mma_bf16(float* d, const uint32_t* a, const uint32_t* b) {
    asm volatile("mma.sync.aligned.m16n8k16.row.col.f32.bf16.bf16.f32 "
        "{%0,%1,%2,%3}, {%4,%5,%6,%7}, {%8,%9}, {%0,%1,%2,%3};"
        : "+f"(d[0]), "+f"(d[1]), "+f"(d[2]), "+f"(d[3])
        : "r"(a[0]), "r"(a[1]), "r"(a[2]), "r"(a[3]), "r"(b[0]), "r"(b[1]));
}

__device__ __forceinline__ void mma_f16(float* d, const uint32_t* a, const uint32_t* b) {
    asm volatile("mma.sync.aligned.m16n8k16.row.col.f32.f16.f16.f32 "
        "{%0,%1,%2,%3}, {%4,%5,%6,%7}, {%8,%9}, {%0,%1,%2,%3};"
        : "+f"(d[0]), "+f"(d[1]), "+f"(d[2]), "+f"(d[3])
        : "r"(a[0]), "r"(a[1]), "r"(a[2]), "r"(a[3]), "r"(b[0]), "r"(b[1]));
}

__device__ __forceinline__ void cp16(uint32_t dst, const void* src) {
    asm volatile("cp.async.cg.shared.global [%0], [%1], 16;" :: "r"(dst), "l"(src));
}

__device__ __forceinline__ float leaky_exp(float eh) {
    eh = (eh > 0.f) ? eh : 0.2f * eh;
    return __expf(eh);
}

// ---------------- conversions + zero emb (single launch) -------------
__global__ void k_cvt(const float* __restrict__ x, const float* __restrict__ W1,
                      const float* __restrict__ W2, const float* __restrict__ W3) {
    int b = blockIdx.x;
    if (b < XBLKS) {
        int i = b * 256 + threadIdx.x;
        float4 v = ((const float4*)x)[i];
        __nv_bfloat16 h0 = __float2bfloat16(v.x), h1 = __float2bfloat16(v.y);
        __nv_bfloat16 h2 = __float2bfloat16(v.z), h3 = __float2bfloat16(v.w);
        __nv_bfloat16 l0 = __float2bfloat16(v.x - __bfloat162float(h0));
        __nv_bfloat16 l1 = __float2bfloat16(v.y - __bfloat162float(h1));
        __nv_bfloat16 l2 = __float2bfloat16(v.z - __bfloat162float(h2));
        __nv_bfloat16 l3 = __float2bfloat16(v.w - __bfloat162float(h3));
        uint2 uh; uh.x = pack_bf(h0, h1); uh.y = pack_bf(h2, h3);
        uint2 ul; ul.x = pack_bf(l0, l1); ul.y = pack_bf(l2, l3);
        ((uint2*)g_xh)[i] = uh;
        ((uint2*)g_xl)[i] = ul;
    } else if (b < XBLKS + W1BLKS) {
        int i = (b - XBLKS) * 256 + threadIdx.x;
        int n = i / Fin, k = i - n * Fin;
        float v = W1[k * HD + n];
        __nv_bfloat16 h = __float2bfloat16(v);
        g_wth[i] = h;
        g_wtl[i] = __float2bfloat16(v - __bfloat162float(h));
    } else if (b < XBLKS + W1BLKS + W23BLKS) {
        int i = (b - XBLKS - W1BLKS) * 256 + threadIdx.x;
        float v;
        if (i < WT2) {
            int n = i / HD, k = i - n * HD;
            v = W2[k * HD + n];
        } else {
            int j = i - WT2; int n = j / HD, k = j - n * HD;
            v = W3[k * HIDD + n];
        }
        __half h = __float2half_rn(v);
        g_w16h[i] = h;
        g_w16l[i] = __float2half_rn(v - __half2float(h));
    } else {
        g_emb[threadIdx.x] = 0.f;
    }
}

// ---------------- CSR build ----------------
__global__ void k_zero() {
    int i = blockIdx.x * blockDim.x + threadIdx.x;
    if (i < Bb * Nn) g_cnt[i] = 0;
}

__global__ void k_hist(const int* __restrict__ ei) {
    const int half = (Bb * Etot) / 2;
    int i = blockIdx.x * blockDim.x + threadIdx.x;
    if (i >= half) return;
#pragma unroll
    for (int r = 0; r < 2; r++) {
        int j = i + r * half;
        int g = j / Etot, e = j - g * Etot;
        int dst = (e < Eraw) ? ei[(g * 2 + 1) * Eraw + e] : (e - Eraw);
        atomicAdd(&g_cnt[g * Nn + dst], 1);
    }
}

__global__ void k_scan() {
    int g = blockIdx.x;
    __shared__ int sh[1024];
    int t = threadIdx.x;
    const int* cnt = g_cnt + g * Nn;
    int b4 = t * 4;
    int v0 = cnt[b4], v1 = cnt[b4 + 1], v2 = cnt[b4 + 2], v3 = cnt[b4 + 3];
    int s1 = v0, s2 = s1 + v1, s3 = s2 + v2, s4 = s3 + v3;
    sh[t] = s4;
    __syncthreads();
    for (int off = 1; off < 1024; off <<= 1) {
        int x = (t >= off) ? sh[t - off] : 0;
        __syncthreads();
        sh[t] += x;
        __syncthreads();
    }
    int base = sh[t] - s4;
    int* rp  = g_rp  + g * (Nn + 1);
    int* cur = g_cur + g * Nn;
    if (t == 0) rp[0] = 0;
    rp[b4 + 1] = base + s1; rp[b4 + 2] = base + s2;
    rp[b4 + 3] = base + s3; rp[b4 + 4] = base + s4;
    cur[b4] = base; cur[b4 + 1] = base + s1; cur[b4 + 2] = base + s2; cur[b4 + 3] = base + s3;
}

__global__ void k_scatter(const int* __restrict__ ei) {
    const int half = (Bb * Etot) / 2;
    int i = blockIdx.x * blockDim.x + threadIdx.x;
    if (i >= half) return;
#pragma unroll
    for (int r = 0; r < 2; r++) {
        int j = i + r * half;
        int g = j / Etot, e = j - g * Etot;
        int src, dst;
        if (e < Eraw) { src = ei[(g * 2) * Eraw + e]; dst = ei[(g * 2 + 1) * Eraw + e]; }
        else          { src = e - Eraw; dst = src; }
        int pos = atomicAdd(&g_cur[g * Nn + dst], 1);
        g_csrc[g * Etot + pos] = src;
    }
}

// ---------------- layer-1 GEMM: bf16 3-term hi/lo, cp.async double-buffered -----------
__global__ __launch_bounds__(256)
void mma_gemm(const __nv_bfloat16* __restrict__ Ah, const __nv_bfloat16* __restrict__ Al,
              const __nv_bfloat16* __restrict__ Bth, const __nv_bfloat16* __restrict__ Btl,
              __half* __restrict__ C, int K,
              const float* __restrict__ atts, const float* __restrict__ attd) {
    extern __shared__ __align__(16) char dsm[];
    __shared__ float sas[128][2], sad[128][2];
    const uint32_t smb = (uint32_t)__cvta_generic_to_shared(dsm);

    const int tid  = threadIdx.x;
    const int lane = tid & 31;
    const int warp = tid >> 5;
    const int wm = warp >> 1, wn = warp & 1;
    const int row0 = blockIdx.y * 128;
    const int head = blockIdx.x;
    const int H = gridDim.x;
    const int Nfull = H * 64;
    const int n0 = head * 64;

    float d[2][4][4];
#pragma unroll
    for (int mi = 0; mi < 2; mi++)
#pragma unroll
        for (int ni = 0; ni < 4; ni++)
#pragma unroll
            for (int j = 0; j < 4; j++) d[mi][ni][j] = 0.f;

    const int a_u0r = tid >> 1, a_u0c = (tid & 1) * 16;
    const int b_u0r = tid >> 2, b_u0c = (tid & 3) * 8;

    auto issue = [&](int ch, int db) {
        const int k0 = ch << 5;
        uint32_t abase = smb + db * SM_A_BUF;
        uint32_t bbase = smb + SM_B_OFF + db * SM_B_BUF;
#pragma unroll
        for (int hl = 0; hl < 2; hl++) {
            const __nv_bfloat16* srcA = (hl ? Al : Ah) + (size_t)(row0 + a_u0r) * K + k0 + a_u0c;
            uint32_t dstA = abase + hl * 10240 + a_u0r * 80 + a_u0c * 2;
            cp16(dstA, srcA);
            cp16(dstA + 16, srcA + 8);
        }
#pragma unroll
        for (int hl = 0; hl < 2; hl++) {
            const __nv_bfloat16* srcB = (hl ? Btl : Bth) + (size_t)(n0 + b_u0r) * K + k0 + b_u0c;
            uint32_t dstB = bbase + hl * 5120 + b_u0r * 80 + b_u0c * 2;
            cp16(dstB, srcB);
        }
        asm volatile("cp.async.commit_group;" ::: "memory");
    };

    const int a_row = wm * 32 + (lane & 15);
    const int a_colbase = (lane >> 4) * 8;
    const int b_rowbase = wn * 32 + (lane >> 4) * 8 + (lane & 7);
    const int b_colbase = ((lane >> 3) & 1) * 8;

    const int nchunks = K >> 5;
    issue(0, 0);
    for (int ch = 0; ch < nchunks; ch++) {
        const int db = ch & 1;
        if (ch + 1 < nchunks) {
            issue(ch + 1, db ^ 1);
            asm volatile("cp.async.wait_group 1;" ::: "memory");
        } else {
            asm volatile("cp.async.wait_group 0;" ::: "memory");
        }
        __syncthreads();

        uint32_t abase = smb + db * SM_A_BUF;
        uint32_t bbase = smb + SM_B_OFF + db * SM_B_BUF;
#pragma unroll
        for (int ks = 0; ks < 2; ks++) {
            uint32_t ah[2][4], al[2][4];
#pragma unroll
            for (int mi = 0; mi < 2; mi++) {
                uint32_t ra = abase + (a_row + mi * 16) * 80 + (ks * 16 + a_colbase) * 2;
                ldsm4u(ah[mi], ra);
                ldsm4u(al[mi], ra + 10240);
            }
            uint32_t bh[4][2], bl[4][2];
#pragma unroll
            for (int nb2 = 0; nb2 < 2; nb2++) {
                uint32_t rb = bbase + (b_rowbase + nb2 * 16) * 80 + (ks * 16 + b_colbase) * 2;
                uint32_t t[4];
                ldsm4u(t, rb);
                bh[nb2 * 2][0] = t[0]; bh[nb2 * 2][1] = t[1];
                bh[nb2 * 2 + 1][0] = t[2]; bh[nb2 * 2 + 1][1] = t[3];
                ldsm4u(t, rb + 5120);
                bl[nb2 * 2][0] = t[0]; bl[nb2 * 2][1] = t[1];
                bl[nb2 * 2 + 1][0] = t[2]; bl[nb2 * 2 + 1][1] = t[3];
            }
#pragma unroll
            for (int mi = 0; mi < 2; mi++)
#pragma unroll
                for (int ni = 0; ni < 4; ni++) {
                    mma_bf16(d[mi][ni], ah[mi], bh[ni]);
                    mma_bf16(d[mi][ni], ah[mi], bl[ni]);
                    mma_bf16(d[mi][ni], al[mi], bh[ni]);
                }
        }
        __syncthreads();
    }

    // ---- epilogue: store C (fp16) + fused attention dots ----
    const float* asp = atts + head * 64;
    const float* adp = attd + head * 64;
    float ps[4] = {0.f, 0.f, 0.f, 0.f}, pd[4] = {0.f, 0.f, 0.f, 0.f};
#pragma unroll
    for (int mi = 0; mi < 2; mi++) {
        int rA = row0 + wm * 32 + mi * 16 + (lane >> 2);
#pragma unroll
        for (int ni = 0; ni < 4; ni++) {
            float* dd = d[mi][ni];
            int c = wn * 32 + ni * 8 + (lane & 3) * 2;
            float2 f0; f0.x = dd[0]; f0.y = dd[1];
            float2 f1; f1.x = dd[2]; f1.y = dd[3];
            *(__half2*)&C[(size_t)rA * Nfull + n0 + c] = __float22half2_rn(f0);
            *(__half2*)&C[(size_t)(rA + 8) * Nfull + n0 + c] = __float22half2_rn(f1);
            float s0 = asp[c], s1 = asp[c + 1], d0 = adp[c], d1 = adp[c + 1];
            ps[mi * 2 + 0] += dd[0] * s0 + dd[1] * s1;
            pd[mi * 2 + 0] += dd[0] * d0 + dd[1] * d1;
            ps[mi * 2 + 1] += dd[2] * s0 + dd[3] * s1;
            pd[mi * 2 + 1] += dd[2] * d0 + dd[3] * d1;
        }
    }
#pragma unroll
    for (int j = 0; j < 4; j++) {
        ps[j] += __shfl_xor_sync(0xffffffffu, ps[j], 1);
        ps[j] += __shfl_xor_sync(0xffffffffu, ps[j], 2);
        pd[j] += __shfl_xor_sync(0xffffffffu, pd[j], 1);
        pd[j] += __shfl_xor_sync(0xffffffffu, pd[j], 2);
    }
    if ((lane & 3) == 0) {
#pragma unroll
        for (int mi = 0; mi < 2; mi++) {
            int rloc = wm * 32 + mi * 16 + (lane >> 2);
            sas[rloc][wn] = ps[mi * 2];     sad[rloc][wn] = pd[mi * 2];
            sas[rloc + 8][wn] = ps[mi * 2 + 1]; sad[rloc + 8][wn] = pd[mi * 2 + 1];
        }
    }
    __syncthreads();
    if (tid < 128) {
        g_as[(size_t)(row0 + tid) * H + head] = sas[tid][0] + sas[tid][1];
        g_ad[(size_t)(row0 + tid) * H + head] = sad[tid][0] + sad[tid][1];
    }
}

// ---------------- layers 2/3 GEMM: fp16 A (single) x fp16 hi/lo B, 2-term ------------
__global__ __launch_bounds__(256)
void mma_gemm_f16(const __half* __restrict__ A,
                  const __half* __restrict__ Bth, const __half* __restrict__ Btl,
                  __half* __restrict__ C, int K,
                  const float* __restrict__ atts, const float* __restrict__ attd) {
    extern __shared__ __align__(16) char dsm[];
    __shared__ float sas[128][2], sad[128][2];
    const uint32_t smb = (uint32_t)__cvta_generic_to_shared(dsm);

    const int tid  = threadIdx.x;
    const int lane = tid & 31;
    const int warp = tid >> 5;
    const int wm = warp >> 1, wn = warp & 1;
    const int row0 = blockIdx.y * 128;
    const int head = blockIdx.x;
    const int H = gridDim.x;
    const int Nfull = H * 64;
    const int n0 = head * 64;

    float d[2][4][4];
#pragma unroll
    for (int mi = 0; mi < 2; mi++)
#pragma unroll
        for (int ni = 0; ni < 4; ni++)
#pragma unroll
            for (int j = 0; j < 4; j++) d[mi][ni][j] = 0.f;

    const int a_u0r = tid >> 1, a_u0c = (tid & 1) * 16;   // halves offset
    const int b_u0r = tid >> 2, b_u0c = (tid & 3) * 8;

    auto issue = [&](int ch, int db) {
        const int k0 = ch << 5;
        uint32_t abase = smb + db * S16_A_BUF;
        uint32_t bbase = smb + S16_B_OFF + db * S16_B_BUF;
        const __half* srcA = A + (size_t)(row0 + a_u0r) * K + k0 + a_u0c;
        uint32_t dstA = abase + a_u0r * 80 + a_u0c * 2;
        cp16(dstA, srcA);
        cp16(dstA + 16, srcA + 8);
#pragma unroll
        for (int hl = 0; hl < 2; hl++) {
            const __half* srcB = (hl ? Btl : Bth) + (size_t)(n0 + b_u0r) * K + k0 + b_u0c;
            uint32_t dstB = bbase + hl * 5120 + b_u0r * 80 + b_u0c * 2;
            cp16(dstB, srcB);
        }
        asm volatile("cp.async.commit_group;" ::: "memory");
    };

    const int a_row = wm * 32 + (lane & 15);
    const int a_colbase = (lane >> 4) * 8;
    const int b_rowbase = wn * 32 + (lane >> 4) * 8 + (lane & 7);
    const int b_colbase = ((lane >> 3) & 1) * 8;

    const int nchunks = K >> 5;
    issue(0, 0);
    for (int ch = 0; ch < nchunks; ch++) {
        const int db = ch & 1;
        if (ch + 1 < nchunks) {
            issue(ch + 1, db ^ 1);
            asm volatile("cp.async.wait_group 1;" ::: "memory");
        } else {
            asm volatile("cp.async.wait_group 0;" ::: "memory");
        }
        __syncthreads();

        uint32_t abase = smb + db * S16_A_BUF;
        uint32_t bbase = smb + S16_B_OFF + db * S16_B_BUF;
#pragma unroll
        for (int ks = 0; ks < 2; ks++) {
            uint32_t af[2][4];
#pragma unroll
            for (int mi = 0; mi < 2; mi++) {
                uint32_t ra = abase + (a_row + mi * 16) * 80 + (ks * 16 + a_colbase) * 2;
                ldsm4u(af[mi], ra);
            }
            uint32_t bh[4][2], bl[4][2];
#pragma unroll
            for (int nb2 = 0; nb2 < 2; nb2++) {
                uint32_t rb = bbase + (b_rowbase + nb2 * 16) * 80 + (ks * 16 + b_colbase) * 2;
                uint32_t t[4];
                ldsm4u(t, rb);
                bh[nb2 * 2][0] = t[0]; bh[nb2 * 2][1] = t[1];
                bh[nb2 * 2 + 1][0] = t[2]; bh[nb2 * 2 + 1][1] = t[3];
                ldsm4u(t, rb + 5120);
                bl[nb2 * 2][0] = t[0]; bl[nb2 * 2][1] = t[1];
                bl[nb2 * 2 + 1][0] = t[2]; bl[nb2 * 2 + 1][1] = t[3];
            }
#pragma unroll
            for (int mi = 0; mi < 2; mi++)
#pragma unroll
                for (int ni = 0; ni < 4; ni++) {
                    mma_f16(d[mi][ni], af[mi], bh[ni]);
                    mma_f16(d[mi][ni], af[mi], bl[ni]);
                }
        }
        __syncthreads();
    }

    // ---- epilogue: store C (fp16) + fused attention dots ----
    const float* asp = atts + head * 64;
    const float* adp = attd + head * 64;
    float ps[4] = {0.f, 0.f, 0.f, 0.f}, pd[4] = {0.f, 0.f, 0.f, 0.f};
#pragma unroll
    for (int mi = 0; mi < 2; mi++) {
        int rA = row0 + wm * 32 + mi * 16 + (lane >> 2);
#pragma unroll
        for (int ni = 0; ni < 4; ni++) {
            float* dd = d[mi][ni];
            int c = wn * 32 + ni * 8 + (lane & 3) * 2;
            float2 f0; f0.x = dd[0]; f0.y = dd[1];
            float2 f1; f1.x = dd[2]; f1.y = dd[3];
            *(__half2*)&C[(size_t)rA * Nfull + n0 + c] = __float22half2_rn(f0);
            *(__half2*)&C[(size_t)(rA + 8) * Nfull + n0 + c] = __float22half2_rn(f1);
            float s0 = asp[c], s1 = asp[c + 1], d0 = adp[c], d1 = adp[c + 1];
            ps[mi * 2 + 0] += dd[0] * s0 + dd[1] * s1;
            pd[mi * 2 + 0] += dd[0] * d0 + dd[1] * d1;
            ps[mi * 2 + 1] += dd[2] * s0 + dd[3] * s1;
            pd[mi * 2 + 1] += dd[2] * d0 + dd[3] * d1;
        }
    }
#pragma unroll
    for (int j = 0; j < 4; j++) {
        ps[j] += __shfl_xor_sync(0xffffffffu, ps[j], 1);
        ps[j] += __shfl_xor_sync(0xffffffffu, ps[j], 2);
        pd[j] += __shfl_xor_sync(0xffffffffu, pd[j], 1);
        pd[j] += __shfl_xor_sync(0xffffffffu, pd[j], 2);
    }
    if ((lane & 3) == 0) {
#pragma unroll
        for (int mi = 0; mi < 2; mi++) {
            int rloc = wm * 32 + mi * 16 + (lane >> 2);
            sas[rloc][wn] = ps[mi * 2];     sad[rloc][wn] = pd[mi * 2];
            sas[rloc + 8][wn] = ps[mi * 2 + 1]; sad[rloc + 8][wn] = pd[mi * 2 + 1];
        }
    }
    __syncthreads();
    if (tid < 128) {
        g_as[(size_t)(row0 + tid) * H + head] = sas[tid][0] + sas[tid][1];
        g_ad[(size_t)(row0 + tid) * H + head] = sad[tid][0] + sad[tid][1];
    }
}

// ---------------- single-pass edge-softmax + aggregation, H=4 (2 warps/node) ----------
// Output: single fp16 buffer (feeds fp16 GEMM A).
template <bool DOELU>
__global__ __launch_bounds__(256)
void attn_agg4(const float* __restrict__ bias) {
    constexpr int H = 4, CH = 256, PER = 8;
    __shared__ float sh_acc[4][32][PER + 1];
    __shared__ float sh_den[4];

    const int tid  = threadIdx.x;
    const int warp = tid >> 5, lane = tid & 31;
    const int pair = warp >> 1, half = warp & 1;
    const int w = blockIdx.x * 4 + pair;
    const int g = w >> 12, n = w & (Nn - 1);
    const int s = g_rp[g * (Nn + 1) + n], e = g_rp[g * (Nn + 1) + n + 1];
    const int mid = (s + e + 1) >> 1;
    const int lo = half ? mid : s;
    const int hi = half ? e : mid;

    const int head = lane >> 3;
    const float adh = g_ad[(size_t)w * H + head];
    const int ebase = g * Etot;
    const long long nb = (long long)g * Nn;

    float acc[PER];
#pragma unroll
    for (int k = 0; k < PER; k++) acc[k] = 0.f;
    float den = 0.f;

    union U4 { uint4 u; __half2 h2[4]; };

    int i = lo;
    for (; i + 2 <= hi; i += 2) {
        int s0 = g_csrc[ebase + i];
        int s1 = g_csrc[ebase + i + 1];
        float ex0 = leaky_exp(g_as[(nb + s0) * H + head] + adh);
        float ex1 = leaky_exp(g_as[(nb + s1) * H + head] + adh);
        den += ex0 + ex1;
        U4 a, b;
        a.u = __ldg((const uint4*)(g_hh + (nb + s0) * CH + lane * PER));
        b.u = __ldg((const uint4*)(g_hh + (nb + s1) * CH + lane * PER));
#pragma unroll
        for (int q = 0; q < 4; q++) {
            float2 fa = __half22float2(a.h2[q]);
            float2 fb = __half22float2(b.h2[q]);
            acc[q * 2 + 0] += ex0 * fa.x + ex1 * fb.x;
            acc[q * 2 + 1] += ex0 * fa.y + ex1 * fb.y;
        }
    }
    if (i < hi) {
        int s0 = g_csrc[ebase + i];
        float ex0 = leaky_exp(g_as[(nb + s0) * H + head] + adh);
        den += ex0;
        U4 a; a.u = __ldg((const uint4*)(g_hh + (nb + s0) * CH + lane * PER));
#pragma unroll
        for (int q = 0; q < 4; q++) {
            float2 fa = __half22float2(a.h2[q]);
            acc[q * 2 + 0] += ex0 * fa.x;
            acc[q * 2 + 1] += ex0 * fa.y;
        }
    }

    if (half == 1) {
#pragma unroll
        for (int k = 0; k < PER; k++) sh_acc[pair][lane][k] = acc[k];
        if (lane == 0) sh_den[pair] = den;
    }
    __syncthreads();
    if (half == 1) return;

#pragma unroll
    for (int k = 0; k < PER; k++) acc[k] += sh_acc[pair][lane][k];
    den += sh_den[pair];

    const float invh = 1.f / (den + 1e-16f);
    float v[PER];
#pragma unroll
    for (int k = 0; k < PER; k++) {
        float t = acc[k] * invh + bias[lane * PER + k];
        if (DOELU) t = (t > 0.f) ? t : expm1f(t);
        v[k] = t;
    }
    union U4o { uint4 u; __half2 h2[4]; } o;
#pragma unroll
    for (int q = 0; q < 4; q++) {
        float2 f; f.x = v[q * 2]; f.y = v[q * 2 + 1];
        o.h2[q] = __float22half2_rn(f);
    }
    *(uint4*)(g_o16 + (size_t)w * CH + lane * PER) = o.u;
}

// ---------------- layer-3 agg (H=1) with FUSED graph-mean ----------------
__global__ __launch_bounds__(256)
void attn_agg1m(const float* __restrict__ bias) {
    __shared__ float sh_sum[64];
    int tid = threadIdx.x;
    int w = (blockIdx.x * blockDim.x + tid) >> 5;
    int lane = tid & 31;
    int g = w >> 12, n = w & (Nn - 1);
    int s = g_rp[g * (Nn + 1) + n], e = g_rp[g * (Nn + 1) + n + 1];
    const float adh = g_ad[w];
    const int ebase = g * Etot;
    const long long nb = (long long)g * Nn;

    if (tid < 64) sh_sum[tid] = 0.f;
    __syncthreads();

    float acc0 = 0.f, acc1 = 0.f, den = 0.f;
    int i = s;
    for (; i + 2 <= e; i += 2) {
        int s0 = g_csrc[ebase + i];
        int s1 = g_csrc[ebase + i + 1];
        float ex0 = leaky_exp(g_as[nb + s0] + adh);
        float ex1 = leaky_exp(g_as[nb + s1] + adh);
        den += ex0 + ex1;
        float2 f0 = __half22float2(__ldg((const __half2*)(g_hh + (nb + s0) * HIDD + lane * 2)));
        float2 f1 = __half22float2(__ldg((const __half2*)(g_hh + (nb + s1) * HIDD + lane * 2)));
        acc0 += ex0 * f0.x + ex1 * f1.x;
        acc1 += ex0 * f0.y + ex1 * f1.y;
    }
    if (i < e) {
        int s0 = g_csrc[ebase + i];
        float ex0 = leaky_exp(g_as[nb + s0] + adh);
        den += ex0;
        float2 f0 = __half22float2(__ldg((const __half2*)(g_hh + (nb + s0) * HIDD + lane * 2)));
        acc0 += ex0 * f0.x;
        acc1 += ex0 * f0.y;
    }
    const float invh = 1.f / (den + 1e-16f);
    float v0 = acc0 * invh + bias[lane * 2];
    float v1 = acc1 * invh + bias[lane * 2 + 1];

    atomicAdd(&sh_sum[lane * 2],     v0);
    atomicAdd(&sh_sum[lane * 2 + 1], v1);
    __syncthreads();
    if (tid < 64)
        atomicAdd(&g_emb[g * HIDD + tid], sh_sum[tid] * (1.f / Nn));
}

// ---------------- classifier + log-softmax + loss/pred ----------------
__global__ void k_final(const int* __restrict__ labels, const float* __restrict__ Wc,
                        const float* __restrict__ bc, float* __restrict__ out, int out_size) {
    __shared__ float lg[Bb][NCLS];
    __shared__ float nll[Bb];
    __shared__ float predf[Bb];
    int t = threadIdx.x;
    if (t < Bb * NCLS) {
        int g = t / NCLS, c = t - g * NCLS;
        float s = bc[c];
#pragma unroll 8
        for (int d = 0; d < HIDD; d++) s += g_emb[g * HIDD + d] * Wc[d * NCLS + c];
        lg[g][c] = s;
    }
    __syncthreads();
    if (t < Bb) {
        float mx = lg[t][0]; int am = 0;
#pragma unroll
        for (int c = 1; c < NCLS; c++) if (lg[t][c] > mx) { mx = lg[t][c]; am = c; }
        float se = 0.f;
#pragma unroll
        for (int c = 0; c < NCLS; c++) se += expf(lg[t][c] - mx);
        float lse = mx + logf(se);
        nll[t] = lse - lg[t][labels[t]];
        predf[t] = (float)am;
    }
    __syncthreads();
    if (t == 0) {
        float loss = (nll[0] + nll[1] + nll[2] + nll[3]) * 0.25f;
        if (out_size >= 9) {
            for (int g = 0; g < Bb; g++) { out[g] = predf[g]; out[4 + g] = (float)labels[g]; }
            out[8] = loss;
            for (int j = 9; j < out_size; j++) out[j] = 0.f;
        } else if (out_size == 1) {
            out[0] = loss;
        } else if (out_size == 4) {
            for (int g = 0; g < Bb; g++) out[g] = predf[g];
        } else if (out_size == 8) {
            for (int g = 0; g < Bb; g++) { out[g] = predf[g]; out[4 + g] = (float)labels[g]; }
        } else {
            for (int j = 0; j < out_size; j++) out[j] = loss;
        }
    }
}

// ---------------- host launcher: r13 topology (ONE side stream, 2 events) -------------
extern "C" void kernel_launch(void* const* d_in, const int* in_sizes, int n_in,
                              void* d_out, int out_size) {
    const float* x      = (const float*)d_in[0];
    const int*   labels = (const int*)  d_in[1];
    const int*   ei     = (const int*)  d_in[2];
    const float* W1  = (const float*)d_in[3];
    const float* as1 = (const float*)d_in[4];
    const float* ad1 = (const float*)d_in[5];
    const float* b1  = (const float*)d_in[6];
    const float* W2  = (const float*)d_in[7];
    const float* as2 = (const float*)d_in[8];
    const float* ad2 = (const float*)d_in[9];
    const float* b2  = (const float*)d_in[10];
    const float* W3  = (const float*)d_in[11];
    const float* as3 = (const float*)d_in[12];
    const float* ad3 = (const float*)d_in[13];
    const float* b3  = (const float*)d_in[14];
    const float* Wc  = (const float*)d_in[15];
    const float* bc  = (const float*)d_in[16];
    float* out = (float*)d_out;

    __half *p_hh, *p_o16, *p_w16h, *p_w16l;
    __nv_bfloat16 *p_xh, *p_xl, *p_wth, *p_wtl;
    cudaGetSymbolAddress((void**)&p_hh,  g_hh);
    cudaGetSymbolAddress((void**)&p_o16, g_o16);
    cudaGetSymbolAddress((void**)&p_xh,  g_xh);
    cudaGetSymbolAddress((void**)&p_xl,  g_xl);
    cudaGetSymbolAddress((void**)&p_wth, g_wth);
    cudaGetSymbolAddress((void**)&p_wtl, g_wtl);
    cudaGetSymbolAddress((void**)&p_w16h, g_w16h);
    cudaGetSymbolAddress((void**)&p_w16l, g_w16l);

    cudaFuncSetAttribute(mma_gemm,     cudaFuncAttributeMaxDynamicSharedMemorySize, SM_DYN);
    cudaFuncSetAttribute(mma_gemm_f16, cudaFuncAttributeMaxDynamicSharedMemorySize, S16_DYN);

    const int M = Mtot;
    const int EBLK2 = ((Bb * Etot) / 2 + 255) / 256;

    // ONE side stream + two events (r13-proven footprint; leaked intentionally,
    // kernel_launch runs only a handful of times)
    cudaStream_t side;
    cudaStreamCreateWithFlags(&side, cudaStreamNonBlocking);
    cudaEvent_t evF, evJ;
    cudaEventCreateWithFlags(&evF, cudaEventDisableTiming);
    cudaEventCreateWithFlags(&evJ, cudaEventDisableTiming);

    cudaEventRecord(evF, 0);
    cudaStreamWaitEvent(side, evF, 0);

    // side: CSR build
    k_zero<<<CNTBLKS, 256, 0, side>>>();
    k_hist<<<EBLK2, 256, 0, side>>>(ei);
    k_scan<<<Bb, 1024, 0, side>>>();
    k_scatter<<<EBLK2, 256, 0, side>>>(ei);
    cudaEventRecord(evJ, side);

    // main: conversions + layer-1 GEMM (bf16 3-term)
    k_cvt<<<XBLKS + W1BLKS + W23BLKS + 1, 256>>>(x, W1, W2, W3);
    mma_gemm<<<dim3(NHEAD, M / 128), 256, SM_DYN>>>(p_xh, p_xl, p_wth, p_wtl, p_hh, Fin, as1, ad1);

    // join + layer-1 agg
    cudaStreamWaitEvent(0, evJ, 0);
    attn_agg4<true><<<M / 4, 256>>>(b1);

    // layer 2 (fp16 2-term)
    mma_gemm_f16<<<dim3(NHEAD, M / 128), 256, S16_DYN>>>(p_o16, p_w16h, p_w16l, p_hh, HD, as2, ad2);
    attn_agg4<true><<<M / 4, 256>>>(b2);

    // layer 3 (fp16 2-term) + fused graph mean
    mma_gemm_f16<<<dim3(1, M / 128), 256, S16_DYN>>>(p_o16, p_w16h + WT2, p_w16l + WT2, p_hh, HD, as3, ad3);
    attn_agg1m<<<M / 8, 256>>>(b3);

    // classifier
    k_final<<<1, 32>>>(labels, Wc, bc, out, out_size);
}